// round 16
// baseline (speedup 1.0000x reference)
#include <cuda_runtime.h>
#include <math.h>

#define HH 384
#define WW 384
#define HWPIX (HH * WW)

typedef unsigned long long u64;

// ---------------- f32x2 packed math helpers (MLP) ----------------
__device__ __forceinline__ u64 pk2(float a, float b) {
    u64 r; asm("mov.b64 %0,{%1,%2};" : "=l"(r) : "f"(a), "f"(b)); return r;
}
__device__ __forceinline__ void upk2(u64 v, float& a, float& b) {
    asm("mov.b64 {%0,%1},%2;" : "=f"(a), "=f"(b) : "l"(v));
}
__device__ __forceinline__ u64 fma2(u64 a, u64 b, u64 c) {
    u64 d; asm("fma.rn.f32x2 %0,%1,%2,%3;" : "=l"(d) : "l"(a), "l"(b), "l"(c)); return d;
}

// ---------------- tf32 helpers ----------------
__device__ __forceinline__ float tf32r(float f) {
    unsigned u; asm("cvt.rna.tf32.f32 %0,%1;" : "=r"(u) : "f"(f));
    return __uint_as_float(u);
}
__device__ __forceinline__ void mma_tf32(float* c, const unsigned* a, unsigned b0, unsigned b1) {
    asm volatile(
        "mma.sync.aligned.m16n8k8.row.col.f32.tf32.tf32.f32 "
        "{%0,%1,%2,%3},{%4,%5,%6,%7},{%8,%9},{%0,%1,%2,%3};"
        : "+f"(c[0]), "+f"(c[1]), "+f"(c[2]), "+f"(c[3])
        : "r"(a[0]), "r"(a[1]), "r"(a[2]), "r"(a[3]), "r"(b0), "r"(b1));
}

// ---------------- static scratch (no allocations allowed) ----------------
__device__ float g_rdmp[128 * HWPIX];
__device__ float g_t1[128 * HWPIX];
__device__ float g_u1[64 * HWPIX];
__device__ float g_u2[64 * HWPIX];

// =====================================================================
// MLP kernel (unchanged from R7): 256 threads, 64 samples / block.
// =====================================================================
#define MPITCH 68
#define SM_MLP_FLOATS (155 * MPITCH + 128 * MPITCH + 27 * 16 + 64)

__global__ __launch_bounds__(256, 2) void mlp_kernel(
    const float* __restrict__ zbufs, const float* __restrict__ ray,
    const int* __restrict__ isTrain,
    const float* __restrict__ w1, const float* __restrict__ b1,
    const float* __restrict__ w2, const float* __restrict__ b2,
    const float* __restrict__ w3, const float* __restrict__ b3)
{
    extern __shared__ float sm[];
    float* bufA  = sm;
    float* h1T   = sm + 155 * MPITCH;
    float* sdpe  = sm + (155 + 128) * MPITCH;
    float* smask = sdpe + 27 * 16;

    const int tid = threadIdx.x;
    const int pixbase = blockIdx.x * 16;
    const float thresh = (*isTrain != 0) ? 0.2f : 0.0f;

    if (tid < 16) {
        int pix = pixbase + tid;
        float dd[3];
        dd[0] = ray[pix * 7 + 3];
        dd[1] = ray[pix * 7 + 4];
        dd[2] = ray[pix * 7 + 5];
        sdpe[0 * 16 + tid] = dd[0];
        sdpe[1 * 16 + tid] = dd[1];
        sdpe[2 * 16 + tid] = dd[2];
        #pragma unroll
        for (int a = 0; a < 3; a++) {
            float sn, cs;
            sincosf(dd[a], &sn, &cs);
            #pragma unroll
            for (int l = 0; l < 4; l++) {
                sdpe[(3 + a * 4 + l) * 16 + tid] = sn;
                sdpe[(15 + a * 4 + l) * 16 + tid] = cs;
                float s2 = 2.0f * sn * cs;
                float c2 = fmaf(-2.0f * sn, sn, 1.0f);
                sn = s2; cs = c2;
            }
        }
    } else if (tid >= 64 && tid < 128) {
        int s = tid - 64;
        int pix = pixbase + (s >> 2);
        int p = s & 3;
        float z = zbufs[pix * 4 + p];
        float ci = 1.0f / ray[pix * 7 + 6];
        #pragma unroll
        for (int j = 0; j < 3; j++)
            bufA[j * MPITCH + s] = ray[pix * 7 + j] + ray[pix * 7 + 3 + j] * z * ci;
        smask[s] = (z > thresh) ? 1.0f : 0.0f;
    }
    __syncthreads();

    if (tid < 192) {
        const int s = tid & 63;
        const int a = tid >> 6;
        float x = bufA[a * MPITCH + s];
        float sn, cs;
        sincosf(x, &sn, &cs);
        float* rs = bufA + (3 + a * 10) * MPITCH + s;
        float* rc = bufA + (33 + a * 10) * MPITCH + s;
        #pragma unroll
        for (int l = 0; l < 10; l++) {
            rs[l * MPITCH] = sn;
            rc[l * MPITCH] = cs;
            float s2 = 2.0f * sn * cs;
            float c2 = fmaf(-2.0f * sn, sn, 1.0f);
            sn = s2; cs = c2;
        }
    }
    __syncthreads();

    const int hh = tid & 63;
    const int g  = tid >> 6;

    {
        u64 A[8], B[8];
        float q0 = b1[hh], q1 = b1[hh + 64];
        #pragma unroll
        for (int i = 0; i < 8; i++) { A[i] = pk2(q0, q0); B[i] = pk2(q1, q1); }

        for (int kc = 0; kc < 56; kc += 8) {
            float wfa[8], wfb[8];
            #pragma unroll
            for (int i = 0; i < 8; i++) {
                wfa[i] = w1[(kc + i) * 128 + hh];
                wfb[i] = w1[(kc + i) * 128 + hh + 64];
            }
            #pragma unroll
            for (int i = 0; i < 8; i++) {
                u64 W0 = pk2(wfa[i], wfa[i]), W1 = pk2(wfb[i], wfb[i]);
                const ulonglong2* xr = (const ulonglong2*)(bufA + (kc + i) * MPITCH + g * 16);
                #pragma unroll
                for (int q = 0; q < 4; q++) {
                    ulonglong2 xv = xr[q];
                    A[2*q]   = fma2(xv.x, W0, A[2*q]);
                    A[2*q+1] = fma2(xv.y, W0, A[2*q+1]);
                    B[2*q]   = fma2(xv.x, W1, B[2*q]);
                    B[2*q+1] = fma2(xv.y, W1, B[2*q+1]);
                }
            }
        }
        {
            float wfa[7], wfb[7];
            #pragma unroll
            for (int i = 0; i < 7; i++) {
                wfa[i] = w1[(56 + i) * 128 + hh];
                wfb[i] = w1[(56 + i) * 128 + hh + 64];
            }
            #pragma unroll
            for (int i = 0; i < 7; i++) {
                u64 W0 = pk2(wfa[i], wfa[i]), W1 = pk2(wfb[i], wfb[i]);
                const ulonglong2* xr = (const ulonglong2*)(bufA + (56 + i) * MPITCH + g * 16);
                #pragma unroll
                for (int q = 0; q < 4; q++) {
                    ulonglong2 xv = xr[q];
                    A[2*q]   = fma2(xv.x, W0, A[2*q]);
                    A[2*q+1] = fma2(xv.y, W0, A[2*q+1]);
                    B[2*q]   = fma2(xv.x, W1, B[2*q]);
                    B[2*q+1] = fma2(xv.y, W1, B[2*q+1]);
                }
            }
        }
        float* r0 = h1T + hh * MPITCH + g * 16;
        float* r1 = h1T + (hh + 64) * MPITCH + g * 16;
        #pragma unroll
        for (int q = 0; q < 4; q++) {
            float f0, f1, f2, f3;
            upk2(A[2*q], f0, f1); upk2(A[2*q+1], f2, f3);
            float4 v0 = { fmaxf(f0,0.f), fmaxf(f1,0.f), fmaxf(f2,0.f), fmaxf(f3,0.f) };
            *(float4*)(r0 + q * 4) = v0;
            upk2(B[2*q], f0, f1); upk2(B[2*q+1], f2, f3);
            float4 v1 = { fmaxf(f0,0.f), fmaxf(f1,0.f), fmaxf(f2,0.f), fmaxf(f3,0.f) };
            *(float4*)(r1 + q * 4) = v1;
        }
    }
    __syncthreads();

    {
        u64 A[8], B[8];
        float q0 = b2[hh], q1 = b2[hh + 64];
        #pragma unroll
        for (int i = 0; i < 8; i++) { A[i] = pk2(q0, q0); B[i] = pk2(q1, q1); }

        for (int kc = 0; kc < 128; kc += 8) {
            float wfa[8], wfb[8];
            #pragma unroll
            for (int i = 0; i < 8; i++) {
                wfa[i] = w2[(kc + i) * 128 + hh];
                wfb[i] = w2[(kc + i) * 128 + hh + 64];
            }
            #pragma unroll
            for (int i = 0; i < 8; i++) {
                u64 W0 = pk2(wfa[i], wfa[i]), W1 = pk2(wfb[i], wfb[i]);
                const ulonglong2* xr = (const ulonglong2*)(h1T + (kc + i) * MPITCH + g * 16);
                #pragma unroll
                for (int q = 0; q < 4; q++) {
                    ulonglong2 xv = xr[q];
                    A[2*q]   = fma2(xv.x, W0, A[2*q]);
                    A[2*q+1] = fma2(xv.y, W0, A[2*q+1]);
                    B[2*q]   = fma2(xv.x, W1, B[2*q]);
                    B[2*q+1] = fma2(xv.y, W1, B[2*q+1]);
                }
            }
        }
        float* r0 = bufA + hh * MPITCH + g * 16;
        float* r1 = bufA + (hh + 64) * MPITCH + g * 16;
        #pragma unroll
        for (int q = 0; q < 4; q++) {
            float f0, f1, f2, f3;
            upk2(A[2*q], f0, f1); upk2(A[2*q+1], f2, f3);
            float4 v0 = { fmaxf(f0,0.f), fmaxf(f1,0.f), fmaxf(f2,0.f), fmaxf(f3,0.f) };
            *(float4*)(r0 + q * 4) = v0;
            upk2(B[2*q], f0, f1); upk2(B[2*q+1], f2, f3);
            float4 v1 = { fmaxf(f0,0.f), fmaxf(f1,0.f), fmaxf(f2,0.f), fmaxf(f3,0.f) };
            *(float4*)(r1 + q * 4) = v1;
        }
    }
    for (int idx = tid; idx < 27 * 64; idx += 256) {
        int kk = idx >> 6, s = idx & 63;
        bufA[(128 + kk) * MPITCH + s] = sdpe[kk * 16 + (s >> 2)];
    }
    __syncthreads();

    {
        const int d = tid & 31, g3 = tid >> 5;
        u64 F[4];
        float bb = b3[d];
        #pragma unroll
        for (int i = 0; i < 4; i++) F[i] = pk2(bb, bb);

        for (int kc = 0; kc < 152; kc += 8) {
            float wf[8];
            #pragma unroll
            for (int i = 0; i < 8; i++) wf[i] = w3[(kc + i) * 32 + d];
            #pragma unroll
            for (int i = 0; i < 8; i++) {
                u64 W = pk2(wf[i], wf[i]);
                const ulonglong2* hr = (const ulonglong2*)(bufA + (kc + i) * MPITCH + g3 * 8);
                #pragma unroll
                for (int q = 0; q < 2; q++) {
                    ulonglong2 xv = hr[q];
                    F[2*q]   = fma2(xv.x, W, F[2*q]);
                    F[2*q+1] = fma2(xv.y, W, F[2*q+1]);
                }
            }
        }
        {
            float wf[3];
            #pragma unroll
            for (int i = 0; i < 3; i++) wf[i] = w3[(152 + i) * 32 + d];
            #pragma unroll
            for (int i = 0; i < 3; i++) {
                u64 W = pk2(wf[i], wf[i]);
                const ulonglong2* hr = (const ulonglong2*)(bufA + (152 + i) * MPITCH + g3 * 8);
                #pragma unroll
                for (int q = 0; q < 2; q++) {
                    ulonglong2 xv = hr[q];
                    F[2*q]   = fma2(xv.x, W, F[2*q]);
                    F[2*q+1] = fma2(xv.y, W, F[2*q+1]);
                }
            }
        }
        float* featT = h1T;
        #pragma unroll
        for (int i = 0; i < 4; i++) {
            int s = g3 * 8 + 2 * i;
            float v0, v1;
            upk2(F[i], v0, v1);
            v0 *= smask[s];
            v1 *= smask[s + 1];
            featT[((s & 3) * 32 + d) * 17 + (s >> 2)] = v0;
            featT[(((s + 1) & 3) * 32 + d) * 17 + ((s + 1) >> 2)] = v1;
        }
    }
    __syncthreads();

    const float* featT = h1T;
    for (int idx = tid; idx < 512; idx += 256) {
        int c = idx >> 2, p4 = (idx & 3) * 4;
        float4 v;
        v.x = featT[c * 17 + p4 + 0];
        v.y = featT[c * 17 + p4 + 1];
        v.z = featT[c * 17 + p4 + 2];
        v.w = featT[c * 17 + p4 + 3];
        *(float4*)&g_rdmp[c * HWPIX + pixbase + p4] = v;
    }
}

// =====================================================================
// Tensor-core conv 3x3 SAME via mma.sync m16n8k8 tf32.
// Tile: 32(x) x 8(y) pixels, 32 output channels per block.
// 8 warps, warp = one pixel row (2 M-tiles of 16) x 32 oc (4 N-tiles).
// ic streamed in chunks of 8 with register prefetch + dbl-buffered smem.
// Input smem [ic8][y10][x pitch36]; weight smem [tap9][k8][oc pitch40]
// (both bank-conflict-free for the mma fragment access patterns).
// MODE 0: relu   MODE 1: aux * sigmoid (gated fuse, in-place safe)
// =====================================================================
#define INCH_SZ 2880   // 8 * 10 * 36
#define WCH_SZ  2880   // 9 * 8 * 40

template <int CIN, int MODE>
__global__ __launch_bounds__(256, 2) void conv_mma_kernel(
    const float* __restrict__ in, const float* __restrict__ w,
    const float* __restrict__ b, float* __restrict__ out,
    const float* __restrict__ aux)
{
    __shared__ float sIn[2][INCH_SZ];
    __shared__ float sW[2][WCH_SZ];

    const int tid = threadIdx.x;
    const int lane = tid & 31;
    const int yl = tid >> 5;          // warp id = local pixel row 0..7
    const int bx = blockIdx.x * 32, by = blockIdx.y * 8;
    const int ocb = blockIdx.z * 32;
    const int NCHUNK = CIN / 8;

    // ---- precompute per-thread gmem offsets for chunk fills ----
    int ioff[12];
    #pragma unroll
    for (int i = 0; i < 12; i++) {
        int idx = tid + i * 256;
        ioff[i] = -1;
        if (idx < INCH_SZ) {
            int ic = idx / 360, rem = idx - ic * 360;
            int yy = rem / 36, xx = rem - yy * 36;
            int gy = by - 1 + yy, gx = bx - 1 + xx;
            if (xx < 34 && gy >= 0 && gy < HH && gx >= 0 && gx < WW)
                ioff[i] = ic * HWPIX + gy * WW + gx;
        }
    }
    int wrel[9];
    #pragma unroll
    for (int i = 0; i < 9; i++) {
        int idx = tid + i * 256;
        wrel[i] = -1;
        if (idx < 2304) {
            int n = idx & 31, k = (idx >> 5) & 7, tap = idx >> 8;
            wrel[i] = (ocb + n) * CIN * 9 + k * 9 + tap;
        }
    }

    // ---- accumulators (init with bias) ----
    float acc[2][4][4];
    {
        #pragma unroll
        for (int nt = 0; nt < 4; nt++) {
            int oc = ocb + nt * 8 + (lane & 3) * 2;
            float bb0 = b[oc], bb1 = b[oc + 1];
            #pragma unroll
            for (int mt = 0; mt < 2; mt++) {
                acc[mt][nt][0] = bb0; acc[mt][nt][1] = bb1;
                acc[mt][nt][2] = bb0; acc[mt][nt][3] = bb1;
            }
        }
    }

    // ---- load chunk 0 ----
    #pragma unroll
    for (int i = 0; i < 12; i++) {
        int idx = tid + i * 256;
        if (idx < INCH_SZ)
            sIn[0][idx] = (ioff[i] >= 0) ? tf32r(in[ioff[i]]) : 0.0f;
    }
    #pragma unroll
    for (int i = 0; i < 9; i++) {
        int idx = tid + i * 256;
        if (idx < 2304) {
            int n = idx & 31, k = (idx >> 5) & 7, tap = idx >> 8;
            sW[0][tap * 320 + k * 40 + n] = tf32r(w[wrel[i]]);
        }
    }
    __syncthreads();

    const int kk = lane & 3, gg = lane >> 2;

    #pragma unroll 1
    for (int c = 0; c < NCHUNK; c++) {
        const int cur = c & 1, nxt = cur ^ 1;
        const bool havenext = (c + 1 < NCHUNK);

        // prefetch next chunk into registers
        float ipf[12], wpf[9];
        if (havenext) {
            const float* inc = in + (c + 1) * 8 * HWPIX;
            #pragma unroll
            for (int i = 0; i < 12; i++)
                ipf[i] = (ioff[i] >= 0) ? tf32r(inc[ioff[i]]) : 0.0f;
            const float* wc = w + (c + 1) * 72;   // 8 ic * 9 taps
            #pragma unroll
            for (int i = 0; i < 9; i++)
                wpf[i] = (wrel[i] >= 0) ? tf32r(wc[wrel[i]]) : 0.0f;
        }

        // compute current chunk: 9 taps x (2 M x 4 N) mma
        const float* Ib = sIn[cur];
        const float* Wb = sW[cur];
        #pragma unroll
        for (int tap = 0; tap < 9; tap++) {
            const int dy = tap / 3, dx = tap - dy * 3;
            const float* Ab = Ib + kk * 360 + (yl + dy) * 36 + gg + dx;
            unsigned a[2][4];
            #pragma unroll
            for (int mt = 0; mt < 2; mt++) {
                a[mt][0] = __float_as_uint(Ab[mt * 16]);
                a[mt][1] = __float_as_uint(Ab[mt * 16 + 8]);
                a[mt][2] = __float_as_uint(Ab[mt * 16 + 1440]);
                a[mt][3] = __float_as_uint(Ab[mt * 16 + 1448]);
            }
            const float* Bb = Wb + tap * 320 + kk * 40 + gg;
            #pragma unroll
            for (int nt = 0; nt < 4; nt++) {
                unsigned b0 = __float_as_uint(Bb[nt * 8]);
                unsigned b1 = __float_as_uint(Bb[160 + nt * 8]);
                mma_tf32(acc[0][nt], a[0], b0, b1);
                mma_tf32(acc[1][nt], a[1], b0, b1);
            }
        }

        // store prefetched chunk
        if (havenext) {
            #pragma unroll
            for (int i = 0; i < 12; i++) {
                int idx = tid + i * 256;
                if (idx < INCH_SZ) sIn[nxt][idx] = ipf[i];
            }
            #pragma unroll
            for (int i = 0; i < 9; i++) {
                int idx = tid + i * 256;
                if (idx < 2304) {
                    int n = idx & 31, k = (idx >> 5) & 7, tap = idx >> 8;
                    sW[nxt][tap * 320 + k * 40 + n] = wpf[i];
                }
            }
        }
        __syncthreads();
    }

    // ---- epilogue ----
    const int y = by + yl;
    #pragma unroll
    for (int mt = 0; mt < 2; mt++) {
        int x = bx + mt * 16 + (lane >> 2);
        #pragma unroll
        for (int nt = 0; nt < 4; nt++) {
            int oc = ocb + nt * 8 + (lane & 3) * 2;
            size_t i00 = (size_t)oc * HWPIX + y * WW + x;          // (oc,   x)
            size_t i10 = i00 + HWPIX;                              // (oc+1, x)
            size_t i01 = i00 + 8;                                  // (oc,   x+8)
            size_t i11 = i10 + 8;                                  // (oc+1, x+8)
            float c0 = acc[mt][nt][0], c1 = acc[mt][nt][1];
            float c2 = acc[mt][nt][2], c3 = acc[mt][nt][3];
            if (MODE == 0) {
                out[i00] = fmaxf(c0, 0.f);
                out[i10] = fmaxf(c1, 0.f);
                out[i01] = fmaxf(c2, 0.f);
                out[i11] = fmaxf(c3, 0.f);
            } else {
                out[i00] = aux[i00] / (1.0f + __expf(-c0));
                out[i10] = aux[i10] / (1.0f + __expf(-c1));
                out[i01] = aux[i01] / (1.0f + __expf(-c2));
                out[i11] = aux[i11] / (1.0f + __expf(-c3));
            }
        }
    }
}

// =====================================================================
// Scalar conv (kept only for the final 64->3 sigmoid conv).
// =====================================================================
#define TLSZ (34 * 68)

template <int CIN, int CT, int MODE>
__global__ __launch_bounds__(256, 2) void conv2_kernel(
    const float* __restrict__ in, const float* __restrict__ w,
    const float* __restrict__ b, float* __restrict__ out,
    const float* __restrict__ aux)
{
    __shared__ __align__(16) float tile[2][TLSZ];
    __shared__ __align__(16) u64 ws2[2][9 * CT];
    __shared__ int soff[10][256];

    const int tid = threadIdx.x;
    const int tx = tid & 15, ty = tid >> 4;
    const int bx = blockIdx.x * 64, by = blockIdx.y * 32;
    const int ocb = blockIdx.z * CT;

    #pragma unroll
    for (int i = 0; i < 10; i++) {
        int idx = tid + i * 256;
        int off = -1;
        if (idx < TLSZ) {
            int row = idx / 68, col = idx - row * 68;
            int gy = by - 1 + row, gx = bx - 1 + col;
            if (col < 66 && gy >= 0 && gy < HH && gx >= 0 && gx < WW)
                off = gy * WW + gx;
        }
        soff[i][tid] = off;
    }

    u64 acc[CT][4];
    #pragma unroll
    for (int o = 0; o < CT; o++) {
        float bb = b[ocb + o];
        u64 bv = pk2(bb, bb);
        #pragma unroll
        for (int i = 0; i < 4; i++) acc[o][i] = bv;
    }

    #pragma unroll
    for (int i = 0; i < 10; i++) {
        int idx = tid + i * 256;
        if (idx < TLSZ) {
            int off = soff[i][tid];
            tile[0][idx] = (off >= 0) ? in[off] : 0.0f;
        }
    }
    if (tid < 9 * CT) {
        int o = tid / 9, j = tid - o * 9;
        float wv = w[(ocb + o) * CIN * 9 + j];
        ws2[0][j * CT + o] = pk2(wv, wv);
    }
    __syncthreads();

    for (int c = 0; c < CIN; c++) {
        const int cur = c & 1, nxt = cur ^ 1;

        float pf[10];
        float wpf = 0.0f;
        const bool havenext = (c + 1 < CIN);
        if (havenext) {
            const float* inc = in + (c + 1) * HWPIX;
            #pragma unroll
            for (int i = 0; i < 10; i++) {
                int off = soff[i][tid];
                pf[i] = (off >= 0) ? inc[off] : 0.0f;
            }
            if (tid < 9 * CT) {
                int o = tid / 9, j = tid - o * 9;
                wpf = w[((ocb + o) * CIN + (c + 1)) * 9 + j];
            }
        }

        const float* T = tile[cur];
        const u64* WS = ws2[cur];
        u64 Pa[5], Pb[5];
        {
            const float* r = T + (ty * 2) * 68 + tx * 4;
            float4 a = *(const float4*)r;
            float2 e = *(const float2*)(r + 4);
            Pa[0] = pk2(a.x, a.y); Pa[1] = pk2(a.y, a.z); Pa[2] = pk2(a.z, a.w);
            Pa[3] = pk2(a.w, e.x); Pa[4] = pk2(e.x, e.y);
            r += 68;
            a = *(const float4*)r; e = *(const float2*)(r + 4);
            Pb[0] = pk2(a.x, a.y); Pb[1] = pk2(a.y, a.z); Pb[2] = pk2(a.z, a.w);
            Pb[3] = pk2(a.w, e.x); Pb[4] = pk2(e.x, e.y);
        }
        #pragma unroll
        for (int jy = 0; jy < 3; jy++) {
            #pragma unroll
            for (int jx = 0; jx < 3; jx++) {
                u64 vA0 = Pa[jx], vB0 = Pa[jx + 2];
                u64 vA1 = Pb[jx], vB1 = Pb[jx + 2];
                #pragma unroll
                for (int o = 0; o < CT; o++) {
                    u64 wv = WS[(jy * 3 + jx) * CT + o];
                    acc[o][0] = fma2(vA0, wv, acc[o][0]);
                    acc[o][1] = fma2(vB0, wv, acc[o][1]);
                    acc[o][2] = fma2(vA1, wv, acc[o][2]);
                    acc[o][3] = fma2(vB1, wv, acc[o][3]);
                }
            }
            if (jy < 2) {
                #pragma unroll
                for (int i = 0; i < 5; i++) Pa[i] = Pb[i];
                const float* r = T + (ty * 2 + jy + 2) * 68 + tx * 4;
                float4 a = *(const float4*)r;
                float2 e = *(const float2*)(r + 4);
                Pb[0] = pk2(a.x, a.y); Pb[1] = pk2(a.y, a.z); Pb[2] = pk2(a.z, a.w);
                Pb[3] = pk2(a.w, e.x); Pb[4] = pk2(e.x, e.y);
            }
        }

        if (havenext) {
            #pragma unroll
            for (int i = 0; i < 10; i++) {
                int idx = tid + i * 256;
                if (idx < TLSZ) tile[nxt][idx] = pf[i];
            }
            if (tid < 9 * CT) {
                int o = tid / 9, j = tid - o * 9;
                ws2[nxt][j * CT + o] = pk2(wpf, wpf);
            }
        }
        __syncthreads();
    }

    const int x0 = bx + tx * 4;
    const int y0 = by + ty * 2;
    #pragma unroll
    for (int o = 0; o < CT; o++) {
        #pragma unroll
        for (int py = 0; py < 2; py++) {
            float f0, f1, f2, f3;
            upk2(acc[o][py * 2 + 0], f0, f1);
            upk2(acc[o][py * 2 + 1], f2, f3);
            if (MODE == 2) {
                float s0 = 1.0f / (1.0f + __expf(-f0));
                float s1 = 1.0f / (1.0f + __expf(-f1));
                float s2 = 1.0f / (1.0f + __expf(-f2));
                float s3 = 1.0f / (1.0f + __expf(-f3));
                int pixr = (y0 + py) * WW + x0;
                out[(pixr + 0) * 3 + ocb + o] = s0;
                out[(pixr + 1) * 3 + ocb + o] = s1;
                out[(pixr + 2) * 3 + ocb + o] = s2;
                out[(pixr + 3) * 3 + ocb + o] = s3;
            } else {
                float4 v = { fmaxf(f0,0.f), fmaxf(f1,0.f), fmaxf(f2,0.f), fmaxf(f3,0.f) };
                *(float4*)&out[(size_t)(ocb + o) * HWPIX + (y0 + py) * WW + x0] = v;
            }
        }
    }
}

// =====================================================================
extern "C" void kernel_launch(void* const* d_in, const int* in_sizes, int n_in,
                              void* d_out, int out_size)
{
    const float* zbufs = (const float*)d_in[0];
    const float* ray   = (const float*)d_in[1];
    const int*   isTr  = (const int*)d_in[4];
    const float* w1 = (const float*)d_in[6];
    const float* b1 = (const float*)d_in[7];
    const float* w2 = (const float*)d_in[8];
    const float* b2 = (const float*)d_in[9];
    const float* w3 = (const float*)d_in[10];
    const float* b3 = (const float*)d_in[11];
    const float* mw1 = (const float*)d_in[12];
    const float* mb1 = (const float*)d_in[13];
    const float* mw2 = (const float*)d_in[14];
    const float* mb2 = (const float*)d_in[15];
    const float* uw1 = (const float*)d_in[16];
    const float* ub1 = (const float*)d_in[17];
    const float* uw2 = (const float*)d_in[18];
    const float* ub2 = (const float*)d_in[19];
    const float* uw3 = (const float*)d_in[20];
    const float* ub3 = (const float*)d_in[21];
    float* out = (float*)d_out;

    float *rdmp, *t1, *u1, *u2;
    cudaGetSymbolAddress((void**)&rdmp, g_rdmp);
    cudaGetSymbolAddress((void**)&t1, g_t1);
    cudaGetSymbolAddress((void**)&u1, g_u1);
    cudaGetSymbolAddress((void**)&u2, g_u2);

    const int mlp_smem = SM_MLP_FLOATS * sizeof(float);
    cudaFuncSetAttribute(mlp_kernel, cudaFuncAttributeMaxDynamicSharedMemorySize, mlp_smem);

    // 1) per-sample MLP -> rdmp (128 x H x W)
    mlp_kernel<<<HWPIX / 16, 256, mlp_smem>>>(zbufs, ray, isTr, w1, b1, w2, b2, w3, b3);

    // 2) m-path conv1: rdmp -> t1 (relu)           [tensor core]
    conv_mma_kernel<128, 0><<<dim3(12, 48, 4), 256>>>(rdmp, mw1, mb1, t1, nullptr);
    // 3) m-path conv2 + sigmoid gate (in-place)    [tensor core]
    conv_mma_kernel<128, 1><<<dim3(12, 48, 4), 256>>>(t1, mw2, mb2, rdmp, rdmp);
    // 4) u1 = relu(conv(fuse, uw1))  128 -> 64     [tensor core]
    conv_mma_kernel<128, 0><<<dim3(12, 48, 2), 256>>>(rdmp, uw1, ub1, u1, nullptr);
    // 5) u2 = relu(conv(u1, uw2))    64 -> 64      [tensor core]
    conv_mma_kernel<64, 0><<<dim3(12, 48, 2), 256>>>(u1, uw2, ub2, u2, nullptr);
    // 6) img = sigmoid(conv(u2, uw3)) 64 -> 3, HWC output  [scalar]
    conv2_kernel<64, 3, 2><<<dim3(6, 12, 1), 256>>>(u2, uw3, ub3, out, nullptr);
}

// round 17
// speedup vs baseline: 1.0025x; 1.0025x over previous
#include <cuda_runtime.h>
#include <math.h>

#define HH 384
#define WW 384
#define HWPIX (HH * WW)

typedef unsigned long long u64;

// ---------------- f32x2 packed math helpers (MLP) ----------------
__device__ __forceinline__ u64 pk2(float a, float b) {
    u64 r; asm("mov.b64 %0,{%1,%2};" : "=l"(r) : "f"(a), "f"(b)); return r;
}
__device__ __forceinline__ void upk2(u64 v, float& a, float& b) {
    asm("mov.b64 {%0,%1},%2;" : "=f"(a), "=f"(b) : "l"(v));
}
__device__ __forceinline__ u64 fma2(u64 a, u64 b, u64 c) {
    u64 d; asm("fma.rn.f32x2 %0,%1,%2,%3;" : "=l"(d) : "l"(a), "l"(b), "l"(c)); return d;
}

// ---------------- tf32 helpers ----------------
__device__ __forceinline__ float tf32r(float f) {
    unsigned u; asm("cvt.rna.tf32.f32 %0,%1;" : "=r"(u) : "f"(f));
    return __uint_as_float(u);
}
__device__ __forceinline__ void mma_tf32(float* c, const unsigned* a, unsigned b0, unsigned b1) {
    asm volatile(
        "mma.sync.aligned.m16n8k8.row.col.f32.tf32.tf32.f32 "
        "{%0,%1,%2,%3},{%4,%5,%6,%7},{%8,%9},{%0,%1,%2,%3};"
        : "+f"(c[0]), "+f"(c[1]), "+f"(c[2]), "+f"(c[3])
        : "r"(a[0]), "r"(a[1]), "r"(a[2]), "r"(a[3]), "r"(b0), "r"(b1));
}

// ---------------- static scratch (no allocations allowed) ----------------
__device__ float g_rdmp[128 * HWPIX];
__device__ float g_t1[128 * HWPIX];
__device__ float g_u1[64 * HWPIX];
__device__ float g_u2[64 * HWPIX];

// =====================================================================
// MLP kernel (unchanged from R7): 256 threads, 64 samples / block.
// =====================================================================
#define MPITCH 68
#define SM_MLP_FLOATS (155 * MPITCH + 128 * MPITCH + 27 * 16 + 64)

__global__ __launch_bounds__(256, 2) void mlp_kernel(
    const float* __restrict__ zbufs, const float* __restrict__ ray,
    const int* __restrict__ isTrain,
    const float* __restrict__ w1, const float* __restrict__ b1,
    const float* __restrict__ w2, const float* __restrict__ b2,
    const float* __restrict__ w3, const float* __restrict__ b3)
{
    extern __shared__ float sm[];
    float* bufA  = sm;
    float* h1T   = sm + 155 * MPITCH;
    float* sdpe  = sm + (155 + 128) * MPITCH;
    float* smask = sdpe + 27 * 16;

    const int tid = threadIdx.x;
    const int pixbase = blockIdx.x * 16;
    const float thresh = (*isTrain != 0) ? 0.2f : 0.0f;

    if (tid < 16) {
        int pix = pixbase + tid;
        float dd[3];
        dd[0] = ray[pix * 7 + 3];
        dd[1] = ray[pix * 7 + 4];
        dd[2] = ray[pix * 7 + 5];
        sdpe[0 * 16 + tid] = dd[0];
        sdpe[1 * 16 + tid] = dd[1];
        sdpe[2 * 16 + tid] = dd[2];
        #pragma unroll
        for (int a = 0; a < 3; a++) {
            float sn, cs;
            sincosf(dd[a], &sn, &cs);
            #pragma unroll
            for (int l = 0; l < 4; l++) {
                sdpe[(3 + a * 4 + l) * 16 + tid] = sn;
                sdpe[(15 + a * 4 + l) * 16 + tid] = cs;
                float s2 = 2.0f * sn * cs;
                float c2 = fmaf(-2.0f * sn, sn, 1.0f);
                sn = s2; cs = c2;
            }
        }
    } else if (tid >= 64 && tid < 128) {
        int s = tid - 64;
        int pix = pixbase + (s >> 2);
        int p = s & 3;
        float z = zbufs[pix * 4 + p];
        float ci = 1.0f / ray[pix * 7 + 6];
        #pragma unroll
        for (int j = 0; j < 3; j++)
            bufA[j * MPITCH + s] = ray[pix * 7 + j] + ray[pix * 7 + 3 + j] * z * ci;
        smask[s] = (z > thresh) ? 1.0f : 0.0f;
    }
    __syncthreads();

    if (tid < 192) {
        const int s = tid & 63;
        const int a = tid >> 6;
        float x = bufA[a * MPITCH + s];
        float sn, cs;
        sincosf(x, &sn, &cs);
        float* rs = bufA + (3 + a * 10) * MPITCH + s;
        float* rc = bufA + (33 + a * 10) * MPITCH + s;
        #pragma unroll
        for (int l = 0; l < 10; l++) {
            rs[l * MPITCH] = sn;
            rc[l * MPITCH] = cs;
            float s2 = 2.0f * sn * cs;
            float c2 = fmaf(-2.0f * sn, sn, 1.0f);
            sn = s2; cs = c2;
        }
    }
    __syncthreads();

    const int hh = tid & 63;
    const int g  = tid >> 6;

    {
        u64 A[8], B[8];
        float q0 = b1[hh], q1 = b1[hh + 64];
        #pragma unroll
        for (int i = 0; i < 8; i++) { A[i] = pk2(q0, q0); B[i] = pk2(q1, q1); }

        for (int kc = 0; kc < 56; kc += 8) {
            float wfa[8], wfb[8];
            #pragma unroll
            for (int i = 0; i < 8; i++) {
                wfa[i] = w1[(kc + i) * 128 + hh];
                wfb[i] = w1[(kc + i) * 128 + hh + 64];
            }
            #pragma unroll
            for (int i = 0; i < 8; i++) {
                u64 W0 = pk2(wfa[i], wfa[i]), W1 = pk2(wfb[i], wfb[i]);
                const ulonglong2* xr = (const ulonglong2*)(bufA + (kc + i) * MPITCH + g * 16);
                #pragma unroll
                for (int q = 0; q < 4; q++) {
                    ulonglong2 xv = xr[q];
                    A[2*q]   = fma2(xv.x, W0, A[2*q]);
                    A[2*q+1] = fma2(xv.y, W0, A[2*q+1]);
                    B[2*q]   = fma2(xv.x, W1, B[2*q]);
                    B[2*q+1] = fma2(xv.y, W1, B[2*q+1]);
                }
            }
        }
        {
            float wfa[7], wfb[7];
            #pragma unroll
            for (int i = 0; i < 7; i++) {
                wfa[i] = w1[(56 + i) * 128 + hh];
                wfb[i] = w1[(56 + i) * 128 + hh + 64];
            }
            #pragma unroll
            for (int i = 0; i < 7; i++) {
                u64 W0 = pk2(wfa[i], wfa[i]), W1 = pk2(wfb[i], wfb[i]);
                const ulonglong2* xr = (const ulonglong2*)(bufA + (56 + i) * MPITCH + g * 16);
                #pragma unroll
                for (int q = 0; q < 4; q++) {
                    ulonglong2 xv = xr[q];
                    A[2*q]   = fma2(xv.x, W0, A[2*q]);
                    A[2*q+1] = fma2(xv.y, W0, A[2*q+1]);
                    B[2*q]   = fma2(xv.x, W1, B[2*q]);
                    B[2*q+1] = fma2(xv.y, W1, B[2*q+1]);
                }
            }
        }
        float* r0 = h1T + hh * MPITCH + g * 16;
        float* r1 = h1T + (hh + 64) * MPITCH + g * 16;
        #pragma unroll
        for (int q = 0; q < 4; q++) {
            float f0, f1, f2, f3;
            upk2(A[2*q], f0, f1); upk2(A[2*q+1], f2, f3);
            float4 v0 = { fmaxf(f0,0.f), fmaxf(f1,0.f), fmaxf(f2,0.f), fmaxf(f3,0.f) };
            *(float4*)(r0 + q * 4) = v0;
            upk2(B[2*q], f0, f1); upk2(B[2*q+1], f2, f3);
            float4 v1 = { fmaxf(f0,0.f), fmaxf(f1,0.f), fmaxf(f2,0.f), fmaxf(f3,0.f) };
            *(float4*)(r1 + q * 4) = v1;
        }
    }
    __syncthreads();

    {
        u64 A[8], B[8];
        float q0 = b2[hh], q1 = b2[hh + 64];
        #pragma unroll
        for (int i = 0; i < 8; i++) { A[i] = pk2(q0, q0); B[i] = pk2(q1, q1); }

        for (int kc = 0; kc < 128; kc += 8) {
            float wfa[8], wfb[8];
            #pragma unroll
            for (int i = 0; i < 8; i++) {
                wfa[i] = w2[(kc + i) * 128 + hh];
                wfb[i] = w2[(kc + i) * 128 + hh + 64];
            }
            #pragma unroll
            for (int i = 0; i < 8; i++) {
                u64 W0 = pk2(wfa[i], wfa[i]), W1 = pk2(wfb[i], wfb[i]);
                const ulonglong2* xr = (const ulonglong2*)(h1T + (kc + i) * MPITCH + g * 16);
                #pragma unroll
                for (int q = 0; q < 4; q++) {
                    ulonglong2 xv = xr[q];
                    A[2*q]   = fma2(xv.x, W0, A[2*q]);
                    A[2*q+1] = fma2(xv.y, W0, A[2*q+1]);
                    B[2*q]   = fma2(xv.x, W1, B[2*q]);
                    B[2*q+1] = fma2(xv.y, W1, B[2*q+1]);
                }
            }
        }
        float* r0 = bufA + hh * MPITCH + g * 16;
        float* r1 = bufA + (hh + 64) * MPITCH + g * 16;
        #pragma unroll
        for (int q = 0; q < 4; q++) {
            float f0, f1, f2, f3;
            upk2(A[2*q], f0, f1); upk2(A[2*q+1], f2, f3);
            float4 v0 = { fmaxf(f0,0.f), fmaxf(f1,0.f), fmaxf(f2,0.f), fmaxf(f3,0.f) };
            *(float4*)(r0 + q * 4) = v0;
            upk2(B[2*q], f0, f1); upk2(B[2*q+1], f2, f3);
            float4 v1 = { fmaxf(f0,0.f), fmaxf(f1,0.f), fmaxf(f2,0.f), fmaxf(f3,0.f) };
            *(float4*)(r1 + q * 4) = v1;
        }
    }
    for (int idx = tid; idx < 27 * 64; idx += 256) {
        int kk = idx >> 6, s = idx & 63;
        bufA[(128 + kk) * MPITCH + s] = sdpe[kk * 16 + (s >> 2)];
    }
    __syncthreads();

    {
        const int d = tid & 31, g3 = tid >> 5;
        u64 F[4];
        float bb = b3[d];
        #pragma unroll
        for (int i = 0; i < 4; i++) F[i] = pk2(bb, bb);

        for (int kc = 0; kc < 152; kc += 8) {
            float wf[8];
            #pragma unroll
            for (int i = 0; i < 8; i++) wf[i] = w3[(kc + i) * 32 + d];
            #pragma unroll
            for (int i = 0; i < 8; i++) {
                u64 W = pk2(wf[i], wf[i]);
                const ulonglong2* hr = (const ulonglong2*)(bufA + (kc + i) * MPITCH + g3 * 8);
                #pragma unroll
                for (int q = 0; q < 2; q++) {
                    ulonglong2 xv = hr[q];
                    F[2*q]   = fma2(xv.x, W, F[2*q]);
                    F[2*q+1] = fma2(xv.y, W, F[2*q+1]);
                }
            }
        }
        {
            float wf[3];
            #pragma unroll
            for (int i = 0; i < 3; i++) wf[i] = w3[(152 + i) * 32 + d];
            #pragma unroll
            for (int i = 0; i < 3; i++) {
                u64 W = pk2(wf[i], wf[i]);
                const ulonglong2* hr = (const ulonglong2*)(bufA + (152 + i) * MPITCH + g3 * 8);
                #pragma unroll
                for (int q = 0; q < 2; q++) {
                    ulonglong2 xv = hr[q];
                    F[2*q]   = fma2(xv.x, W, F[2*q]);
                    F[2*q+1] = fma2(xv.y, W, F[2*q+1]);
                }
            }
        }
        float* featT = h1T;
        #pragma unroll
        for (int i = 0; i < 4; i++) {
            int s = g3 * 8 + 2 * i;
            float v0, v1;
            upk2(F[i], v0, v1);
            v0 *= smask[s];
            v1 *= smask[s + 1];
            featT[((s & 3) * 32 + d) * 17 + (s >> 2)] = v0;
            featT[(((s + 1) & 3) * 32 + d) * 17 + ((s + 1) >> 2)] = v1;
        }
    }
    __syncthreads();

    const float* featT = h1T;
    for (int idx = tid; idx < 512; idx += 256) {
        int c = idx >> 2, p4 = (idx & 3) * 4;
        float4 v;
        v.x = featT[c * 17 + p4 + 0];
        v.y = featT[c * 17 + p4 + 1];
        v.z = featT[c * 17 + p4 + 2];
        v.w = featT[c * 17 + p4 + 3];
        *(float4*)&g_rdmp[c * HWPIX + pixbase + p4] = v;
    }
}

// =====================================================================
// Tensor-core conv 3x3 SAME via mma.sync m16n8k8 tf32.
// Tile: 32(x) x 8(y) pixels, 32 output channels per block.
// 8 warps, warp = one pixel row (2 M-tiles of 16) x 32 oc (4 N-tiles).
// ic streamed in chunks of 8 with register prefetch + dbl-buffered smem.
// Input smem [ic8][y10][x pitch36]; weight smem [tap9][k8][oc pitch40]
// (both bank-conflict-free for the mma fragment access patterns).
// MODE 0: relu   MODE 1: aux * sigmoid (gated fuse, in-place safe)
// =====================================================================
#define INCH_SZ 2880   // 8 * 10 * 36
#define WCH_SZ  2880   // 9 * 8 * 40

template <int CIN, int MODE>
__global__ __launch_bounds__(256, 2) void conv_mma_kernel(
    const float* __restrict__ in, const float* __restrict__ w,
    const float* __restrict__ b, float* __restrict__ out,
    const float* __restrict__ aux)
{
    __shared__ float sIn[2][INCH_SZ];
    __shared__ float sW[2][WCH_SZ];

    const int tid = threadIdx.x;
    const int lane = tid & 31;
    const int yl = tid >> 5;          // warp id = local pixel row 0..7
    const int bx = blockIdx.x * 32, by = blockIdx.y * 8;
    const int ocb = blockIdx.z * 32;
    const int NCHUNK = CIN / 8;

    // ---- precompute per-thread gmem offsets for chunk fills ----
    int ioff[12];
    #pragma unroll
    for (int i = 0; i < 12; i++) {
        int idx = tid + i * 256;
        ioff[i] = -1;
        if (idx < INCH_SZ) {
            int ic = idx / 360, rem = idx - ic * 360;
            int yy = rem / 36, xx = rem - yy * 36;
            int gy = by - 1 + yy, gx = bx - 1 + xx;
            if (xx < 34 && gy >= 0 && gy < HH && gx >= 0 && gx < WW)
                ioff[i] = ic * HWPIX + gy * WW + gx;
        }
    }
    int wrel[9];
    #pragma unroll
    for (int i = 0; i < 9; i++) {
        int idx = tid + i * 256;
        wrel[i] = -1;
        if (idx < 2304) {
            int n = idx & 31, k = (idx >> 5) & 7, tap = idx >> 8;
            wrel[i] = (ocb + n) * CIN * 9 + k * 9 + tap;
        }
    }

    // ---- accumulators (init with bias) ----
    float acc[2][4][4];
    {
        #pragma unroll
        for (int nt = 0; nt < 4; nt++) {
            int oc = ocb + nt * 8 + (lane & 3) * 2;
            float bb0 = b[oc], bb1 = b[oc + 1];
            #pragma unroll
            for (int mt = 0; mt < 2; mt++) {
                acc[mt][nt][0] = bb0; acc[mt][nt][1] = bb1;
                acc[mt][nt][2] = bb0; acc[mt][nt][3] = bb1;
            }
        }
    }

    // ---- load chunk 0 ----
    #pragma unroll
    for (int i = 0; i < 12; i++) {
        int idx = tid + i * 256;
        if (idx < INCH_SZ)
            sIn[0][idx] = (ioff[i] >= 0) ? tf32r(in[ioff[i]]) : 0.0f;
    }
    #pragma unroll
    for (int i = 0; i < 9; i++) {
        int idx = tid + i * 256;
        if (idx < 2304) {
            int n = idx & 31, k = (idx >> 5) & 7, tap = idx >> 8;
            sW[0][tap * 320 + k * 40 + n] = tf32r(w[wrel[i]]);
        }
    }
    __syncthreads();

    const int kk = lane & 3, gg = lane >> 2;

    #pragma unroll 1
    for (int c = 0; c < NCHUNK; c++) {
        const int cur = c & 1, nxt = cur ^ 1;
        const bool havenext = (c + 1 < NCHUNK);

        // prefetch next chunk into registers
        float ipf[12], wpf[9];
        if (havenext) {
            const float* inc = in + (c + 1) * 8 * HWPIX;
            #pragma unroll
            for (int i = 0; i < 12; i++)
                ipf[i] = (ioff[i] >= 0) ? tf32r(inc[ioff[i]]) : 0.0f;
            const float* wc = w + (c + 1) * 72;   // 8 ic * 9 taps
            #pragma unroll
            for (int i = 0; i < 9; i++)
                wpf[i] = (wrel[i] >= 0) ? tf32r(wc[wrel[i]]) : 0.0f;
        }

        // compute current chunk: 9 taps x (2 M x 4 N) mma
        const float* Ib = sIn[cur];
        const float* Wb = sW[cur];
        #pragma unroll
        for (int tap = 0; tap < 9; tap++) {
            const int dy = tap / 3, dx = tap - dy * 3;
            const float* Ab = Ib + kk * 360 + (yl + dy) * 36 + gg + dx;
            unsigned a[2][4];
            #pragma unroll
            for (int mt = 0; mt < 2; mt++) {
                a[mt][0] = __float_as_uint(Ab[mt * 16]);
                a[mt][1] = __float_as_uint(Ab[mt * 16 + 8]);
                a[mt][2] = __float_as_uint(Ab[mt * 16 + 1440]);
                a[mt][3] = __float_as_uint(Ab[mt * 16 + 1448]);
            }
            const float* Bb = Wb + tap * 320 + kk * 40 + gg;
            #pragma unroll
            for (int nt = 0; nt < 4; nt++) {
                unsigned b0 = __float_as_uint(Bb[nt * 8]);
                unsigned b1 = __float_as_uint(Bb[160 + nt * 8]);
                mma_tf32(acc[0][nt], a[0], b0, b1);
                mma_tf32(acc[1][nt], a[1], b0, b1);
            }
        }

        // store prefetched chunk
        if (havenext) {
            #pragma unroll
            for (int i = 0; i < 12; i++) {
                int idx = tid + i * 256;
                if (idx < INCH_SZ) sIn[nxt][idx] = ipf[i];
            }
            #pragma unroll
            for (int i = 0; i < 9; i++) {
                int idx = tid + i * 256;
                if (idx < 2304) {
                    int n = idx & 31, k = (idx >> 5) & 7, tap = idx >> 8;
                    sW[nxt][tap * 320 + k * 40 + n] = wpf[i];
                }
            }
        }
        __syncthreads();
    }

    // ---- epilogue ----
    const int y = by + yl;
    #pragma unroll
    for (int mt = 0; mt < 2; mt++) {
        int x = bx + mt * 16 + (lane >> 2);
        #pragma unroll
        for (int nt = 0; nt < 4; nt++) {
            int oc = ocb + nt * 8 + (lane & 3) * 2;
            size_t i00 = (size_t)oc * HWPIX + y * WW + x;          // (oc,   x)
            size_t i10 = i00 + HWPIX;                              // (oc+1, x)
            size_t i01 = i00 + 8;                                  // (oc,   x+8)
            size_t i11 = i10 + 8;                                  // (oc+1, x+8)
            float c0 = acc[mt][nt][0], c1 = acc[mt][nt][1];
            float c2 = acc[mt][nt][2], c3 = acc[mt][nt][3];
            if (MODE == 0) {
                out[i00] = fmaxf(c0, 0.f);
                out[i10] = fmaxf(c1, 0.f);
                out[i01] = fmaxf(c2, 0.f);
                out[i11] = fmaxf(c3, 0.f);
            } else {
                out[i00] = aux[i00] / (1.0f + __expf(-c0));
                out[i10] = aux[i10] / (1.0f + __expf(-c1));
                out[i01] = aux[i01] / (1.0f + __expf(-c2));
                out[i11] = aux[i11] / (1.0f + __expf(-c3));
            }
        }
    }
}

// =====================================================================
// Scalar conv (kept only for the final 64->3 sigmoid conv).
// =====================================================================
#define TLSZ (34 * 68)

template <int CIN, int CT, int MODE>
__global__ __launch_bounds__(256, 2) void conv2_kernel(
    const float* __restrict__ in, const float* __restrict__ w,
    const float* __restrict__ b, float* __restrict__ out,
    const float* __restrict__ aux)
{
    __shared__ __align__(16) float tile[2][TLSZ];
    __shared__ __align__(16) u64 ws2[2][9 * CT];
    __shared__ int soff[10][256];

    const int tid = threadIdx.x;
    const int tx = tid & 15, ty = tid >> 4;
    const int bx = blockIdx.x * 64, by = blockIdx.y * 32;
    const int ocb = blockIdx.z * CT;

    #pragma unroll
    for (int i = 0; i < 10; i++) {
        int idx = tid + i * 256;
        int off = -1;
        if (idx < TLSZ) {
            int row = idx / 68, col = idx - row * 68;
            int gy = by - 1 + row, gx = bx - 1 + col;
            if (col < 66 && gy >= 0 && gy < HH && gx >= 0 && gx < WW)
                off = gy * WW + gx;
        }
        soff[i][tid] = off;
    }

    u64 acc[CT][4];
    #pragma unroll
    for (int o = 0; o < CT; o++) {
        float bb = b[ocb + o];
        u64 bv = pk2(bb, bb);
        #pragma unroll
        for (int i = 0; i < 4; i++) acc[o][i] = bv;
    }

    #pragma unroll
    for (int i = 0; i < 10; i++) {
        int idx = tid + i * 256;
        if (idx < TLSZ) {
            int off = soff[i][tid];
            tile[0][idx] = (off >= 0) ? in[off] : 0.0f;
        }
    }
    if (tid < 9 * CT) {
        int o = tid / 9, j = tid - o * 9;
        float wv = w[(ocb + o) * CIN * 9 + j];
        ws2[0][j * CT + o] = pk2(wv, wv);
    }
    __syncthreads();

    for (int c = 0; c < CIN; c++) {
        const int cur = c & 1, nxt = cur ^ 1;

        float pf[10];
        float wpf = 0.0f;
        const bool havenext = (c + 1 < CIN);
        if (havenext) {
            const float* inc = in + (c + 1) * HWPIX;
            #pragma unroll
            for (int i = 0; i < 10; i++) {
                int off = soff[i][tid];
                pf[i] = (off >= 0) ? inc[off] : 0.0f;
            }
            if (tid < 9 * CT) {
                int o = tid / 9, j = tid - o * 9;
                wpf = w[((ocb + o) * CIN + (c + 1)) * 9 + j];
            }
        }

        const float* T = tile[cur];
        const u64* WS = ws2[cur];
        u64 Pa[5], Pb[5];
        {
            const float* r = T + (ty * 2) * 68 + tx * 4;
            float4 a = *(const float4*)r;
            float2 e = *(const float2*)(r + 4);
            Pa[0] = pk2(a.x, a.y); Pa[1] = pk2(a.y, a.z); Pa[2] = pk2(a.z, a.w);
            Pa[3] = pk2(a.w, e.x); Pa[4] = pk2(e.x, e.y);
            r += 68;
            a = *(const float4*)r; e = *(const float2*)(r + 4);
            Pb[0] = pk2(a.x, a.y); Pb[1] = pk2(a.y, a.z); Pb[2] = pk2(a.z, a.w);
            Pb[3] = pk2(a.w, e.x); Pb[4] = pk2(e.x, e.y);
        }
        #pragma unroll
        for (int jy = 0; jy < 3; jy++) {
            #pragma unroll
            for (int jx = 0; jx < 3; jx++) {
                u64 vA0 = Pa[jx], vB0 = Pa[jx + 2];
                u64 vA1 = Pb[jx], vB1 = Pb[jx + 2];
                #pragma unroll
                for (int o = 0; o < CT; o++) {
                    u64 wv = WS[(jy * 3 + jx) * CT + o];
                    acc[o][0] = fma2(vA0, wv, acc[o][0]);
                    acc[o][1] = fma2(vB0, wv, acc[o][1]);
                    acc[o][2] = fma2(vA1, wv, acc[o][2]);
                    acc[o][3] = fma2(vB1, wv, acc[o][3]);
                }
            }
            if (jy < 2) {
                #pragma unroll
                for (int i = 0; i < 5; i++) Pa[i] = Pb[i];
                const float* r = T + (ty * 2 + jy + 2) * 68 + tx * 4;
                float4 a = *(const float4*)r;
                float2 e = *(const float2*)(r + 4);
                Pb[0] = pk2(a.x, a.y); Pb[1] = pk2(a.y, a.z); Pb[2] = pk2(a.z, a.w);
                Pb[3] = pk2(a.w, e.x); Pb[4] = pk2(e.x, e.y);
            }
        }

        if (havenext) {
            #pragma unroll
            for (int i = 0; i < 10; i++) {
                int idx = tid + i * 256;
                if (idx < TLSZ) tile[nxt][idx] = pf[i];
            }
            if (tid < 9 * CT) {
                int o = tid / 9, j = tid - o * 9;
                ws2[nxt][j * CT + o] = pk2(wpf, wpf);
            }
        }
        __syncthreads();
    }

    const int x0 = bx + tx * 4;
    const int y0 = by + ty * 2;
    #pragma unroll
    for (int o = 0; o < CT; o++) {
        #pragma unroll
        for (int py = 0; py < 2; py++) {
            float f0, f1, f2, f3;
            upk2(acc[o][py * 2 + 0], f0, f1);
            upk2(acc[o][py * 2 + 1], f2, f3);
            if (MODE == 2) {
                float s0 = 1.0f / (1.0f + __expf(-f0));
                float s1 = 1.0f / (1.0f + __expf(-f1));
                float s2 = 1.0f / (1.0f + __expf(-f2));
                float s3 = 1.0f / (1.0f + __expf(-f3));
                int pixr = (y0 + py) * WW + x0;
                out[(pixr + 0) * 3 + ocb + o] = s0;
                out[(pixr + 1) * 3 + ocb + o] = s1;
                out[(pixr + 2) * 3 + ocb + o] = s2;
                out[(pixr + 3) * 3 + ocb + o] = s3;
            } else {
                float4 v = { fmaxf(f0,0.f), fmaxf(f1,0.f), fmaxf(f2,0.f), fmaxf(f3,0.f) };
                *(float4*)&out[(size_t)(ocb + o) * HWPIX + (y0 + py) * WW + x0] = v;
            }
        }
    }
}

// =====================================================================
extern "C" void kernel_launch(void* const* d_in, const int* in_sizes, int n_in,
                              void* d_out, int out_size)
{
    const float* zbufs = (const float*)d_in[0];
    const float* ray   = (const float*)d_in[1];
    const int*   isTr  = (const int*)d_in[4];
    const float* w1 = (const float*)d_in[6];
    const float* b1 = (const float*)d_in[7];
    const float* w2 = (const float*)d_in[8];
    const float* b2 = (const float*)d_in[9];
    const float* w3 = (const float*)d_in[10];
    const float* b3 = (const float*)d_in[11];
    const float* mw1 = (const float*)d_in[12];
    const float* mb1 = (const float*)d_in[13];
    const float* mw2 = (const float*)d_in[14];
    const float* mb2 = (const float*)d_in[15];
    const float* uw1 = (const float*)d_in[16];
    const float* ub1 = (const float*)d_in[17];
    const float* uw2 = (const float*)d_in[18];
    const float* ub2 = (const float*)d_in[19];
    const float* uw3 = (const float*)d_in[20];
    const float* ub3 = (const float*)d_in[21];
    float* out = (float*)d_out;

    float *rdmp, *t1, *u1, *u2;
    cudaGetSymbolAddress((void**)&rdmp, g_rdmp);
    cudaGetSymbolAddress((void**)&t1, g_t1);
    cudaGetSymbolAddress((void**)&u1, g_u1);
    cudaGetSymbolAddress((void**)&u2, g_u2);

    const int mlp_smem = SM_MLP_FLOATS * sizeof(float);
    cudaFuncSetAttribute(mlp_kernel, cudaFuncAttributeMaxDynamicSharedMemorySize, mlp_smem);

    // 1) per-sample MLP -> rdmp (128 x H x W)
    mlp_kernel<<<HWPIX / 16, 256, mlp_smem>>>(zbufs, ray, isTr, w1, b1, w2, b2, w3, b3);

    // 2) m-path conv1: rdmp -> t1 (relu)           [tensor core]
    conv_mma_kernel<128, 0><<<dim3(12, 48, 4), 256>>>(rdmp, mw1, mb1, t1, nullptr);
    // 3) m-path conv2 + sigmoid gate (in-place)    [tensor core]
    conv_mma_kernel<128, 1><<<dim3(12, 48, 4), 256>>>(t1, mw2, mb2, rdmp, rdmp);
    // 4) u1 = relu(conv(fuse, uw1))  128 -> 64     [tensor core]
    conv_mma_kernel<128, 0><<<dim3(12, 48, 2), 256>>>(rdmp, uw1, ub1, u1, nullptr);
    // 5) u2 = relu(conv(u1, uw2))    64 -> 64      [tensor core]
    conv_mma_kernel<64, 0><<<dim3(12, 48, 2), 256>>>(u1, uw2, ub2, u2, nullptr);
    // 6) img = sigmoid(conv(u2, uw3)) 64 -> 3, HWC output  [scalar]
    conv2_kernel<64, 3, 2><<<dim3(6, 12, 1), 256>>>(u2, uw3, ub3, out, nullptr);
}